// round 15
// baseline (speedup 1.0000x reference)
#include <cuda_runtime.h>
#include <math.h>

// MFHawkes factorized O(B*L*D): 1 cluster per batch, HW cluster barrier.
//   t = times/1e4, ab = |beta|, ep_i = exp(ab*t_i), C = exp(-ab*t_last)
//   w_j = ep_j*mask_j ; g_j = 1 - ep_j*C ; P_i = sum_{j<i} w_j e_j
//   v = sum_j g_j e_j ; E = sum_i e_i
//   -log(lam_i) = -log(|ab*(e_i.P_i) + u_i*ep_i| + 1e-6*ep_i) + ab*t_i
//   out[b] = sum_i(-log lam_i) + ab*sum(t) + horizon*sum(u) + E.v

#define HK_L     2048
#define HK_D     64
#define HK_B     4
#define HK_CHUNK 16                     // events per warp
#define HK_WPB   16                     // warps per block (512 threads)
#define HK_EPB   (HK_WPB * HK_CHUNK)    // 256 events per block
#define HK_BPB   (HK_L / HK_EPB)        // 8 blocks per batch = cluster size
#define HK_NBLK  (HK_B * HK_BPB)        // 32 blocks

__device__ float g_T[HK_NBLK * HK_D];
__device__ float g_V[HK_NBLK * HK_D];
__device__ float g_E[HK_NBLK * HK_D];

__global__ __launch_bounds__(HK_WPB * 32, 1) __cluster_dims__(HK_BPB, 1, 1)
void mfhawkes_fused(const int*   __restrict__ ids,
                    const float* __restrict__ times,
                    const float* __restrict__ mask,
                    const float* __restrict__ emb,
                    const float* __restrict__ u_table,
                    const float* __restrict__ beta,
                    float*       __restrict__ out)
{
    __shared__ float Tsm[HK_WPB][HK_D];
    __shared__ float Vsm[HK_WPB][HK_D];
    __shared__ float Esm[HK_WPB][HK_D];
    __shared__ float basesm[HK_D];
    __shared__ float prodsm[HK_D];
    __shared__ float racc[HK_WPB];

    const int tid    = threadIdx.x;
    const int warp   = tid >> 5;
    const int lane   = tid & 31;
    const int batch  = blockIdx.x / HK_BPB;
    const int blk_in = blockIdx.x % HK_BPB;

    const float ab      = fabsf(beta[0]);
    const float tlast   = times[batch * HK_L + HK_L - 1] * (1.0f / 10000.0f);
    const float horizon = tlast - times[batch * HK_L + 1] * (1.0f / 10000.0f);
    const float C       = __expf(-ab * tlast);

    if (blk_in == 0 && tid == 0) out[batch] = 0.0f;   // ordered before peers' adds by cluster barrier

    // ---- Phase A: per-quad vector loads fused into gather (no staging arrays)
    const int i0 = batch * HK_L + blk_in * HK_EPB + warp * HK_CHUNK;  // mult of 16

    float e0[HK_CHUNK], e1[HK_CHUNK], w[HK_CHUNK], ue[HK_CHUNK], pe[HK_CHUNK];
    float T0 = 0.f, T1 = 0.f, V0 = 0.f, V1 = 0.f, E0 = 0.f, E1 = 0.f;
    float tsum = 0.f, usum = 0.f;

    #pragma unroll
    for (int q = 0; q < HK_CHUNK / 4; q++) {
        const int4   iv = ((const int4*)  (ids   + i0))[q];
        const float4 tv = ((const float4*)(times + i0))[q];
        const float4 mv = ((const float4*)(mask  + i0))[q];
        const int   idq[4] = {iv.x, iv.y, iv.z, iv.w};
        const float tq [4] = {tv.x, tv.y, tv.z, tv.w};
        const float mq [4] = {mv.x, mv.y, mv.z, mv.w};
        #pragma unroll
        for (int j = 0; j < 4; j++) {
            const int   i  = q * 4 + j;
            const int   id = idq[j];
            const float ti = tq[j] * (1.0f / 10000.0f);
            e0[i] = emb[id * HK_D + lane];
            e1[i] = emb[id * HK_D + lane + 32];
            const float uu  = fabsf(u_table[id]);
            const float epi = __expf(ab * ti);
            w[i]  = epi * mq[j];
            ue[i] = uu * epi;
            pe[i] = 1e-6f * epi;
            const float g = 1.0f - epi * C;
            T0 += w[i] * e0[i];  T1 += w[i] * e1[i];
            V0 += g    * e0[i];  V1 += g    * e1[i];
            E0 += e0[i];         E1 += e1[i];
            tsum += ti;  usum += uu;
        }
    }
    Tsm[warp][lane] = T0;  Tsm[warp][lane + 32] = T1;
    Vsm[warp][lane] = V0;  Vsm[warp][lane + 32] = V1;
    Esm[warp][lane] = E0;  Esm[warp][lane + 32] = E1;
    __syncthreads();

    // ---- publish block totals
    if (tid < HK_D) {
        const int d = tid;
        float tt = 0.f, vv = 0.f, ee = 0.f;
        #pragma unroll
        for (int c = 0; c < HK_WPB; c++) {
            tt += Tsm[c][d];
            vv += Vsm[c][d];
            ee += Esm[c][d];
        }
        g_T[blockIdx.x * HK_D + d] = tt;
        g_V[blockIdx.x * HK_D + d] = vv;
        g_E[blockIdx.x * HK_D + d] = ee;
    }

    // ---- hardware cluster barrier (release/acquire at cluster scope)
    asm volatile("barrier.cluster.arrive.aligned;" ::: "memory");
    asm volatile("barrier.cluster.wait.aligned;"   ::: "memory");

    // ---- cross-block exclusive base (only blk_in rows); leader computes E_d*v_d
    if (tid < HK_D) {
        const int d = tid;
        float base = 0.f;
        for (int k = 0; k < blk_in; k++)
            base += g_T[(batch * HK_BPB + k) * HK_D + d];
        basesm[d] = base;
        if (blk_in == 0) {
            float vv = 0.f, ee = 0.f;
            #pragma unroll
            for (int k = 0; k < HK_BPB; k++) {
                vv += g_V[(batch * HK_BPB + k) * HK_D + d];
                ee += g_E[(batch * HK_BPB + k) * HK_D + d];
            }
            prodsm[d] = vv * ee;
        }
    }
    __syncthreads();

    // ---- Phase C: per-warp base, FFMA P-chain, batched reduce, fused logs
    {
        float P0 = basesm[lane];
        float P1 = basesm[lane + 32];
        #pragma unroll
        for (int c = 0; c < HK_WPB - 1; c++) {
            const float a0 = Tsm[c][lane];
            const float a1 = Tsm[c][lane + 32];
            if (c < warp) { P0 += a0; P1 += a1; }
        }
        float d1[HK_CHUNK];
        #pragma unroll
        for (int i = 0; i < HK_CHUNK; i++) {
            d1[i] = e0[i] * P0 + e1[i] * P1;
            P0 += w[i] * e0[i];
            P1 += w[i] * e1[i];
        }
        #pragma unroll
        for (int off = 16; off; off >>= 1) {
            #pragma unroll
            for (int i = 0; i < HK_CHUNK; i++)
                d1[i] += __shfl_xor_sync(0xffffffffu, d1[i], off);
        }
        // tail: acc = ab*sum(t) + horizon*sum(u) - sum(log(arg)), logs fused 4-wide
        float acc = ab * tsum + horizon * usum;
        #pragma unroll
        for (int gq = 0; gq < HK_CHUNK / 4; gq++) {
            float p = 1.0f;
            #pragma unroll
            for (int j = 0; j < 4; j++) {
                const int   i   = gq * 4 + j;
                const float A   = ab * d1[i] + ue[i];
                const float arg = fabsf(A) + pe[i];
                p *= arg;
            }
            acc -= __logf(p);
        }
        if (lane == 0) racc[warp] = acc;
    }
    __syncthreads();

    if (warp == 0) {
        float a = (lane < HK_WPB) ? racc[lane] : 0.f;
        #pragma unroll
        for (int off = 8; off; off >>= 1)
            a += __shfl_xor_sync(0xffffffffu, a, off);
        float extra = 0.f;
        if (blk_in == 0) {
            float p = prodsm[lane] + prodsm[lane + 32];
            #pragma unroll
            for (int off = 16; off; off >>= 1)
                p += __shfl_xor_sync(0xffffffffu, p, off);
            extra = p;
        }
        if (lane == 0) atomicAdd(&out[batch], a + extra);
    }
}

extern "C" void kernel_launch(void* const* d_in, const int* in_sizes, int n_in,
                              void* d_out, int out_size)
{
    const int*   ids     = (const int*)  d_in[0];
    const float* times   = (const float*)d_in[1];
    const float* mask    = (const float*)d_in[2];
    const float* emb     = (const float*)d_in[3];
    const float* u_table = (const float*)d_in[4];
    const float* beta    = (const float*)d_in[5];
    float*       out     = (float*)d_out;

    mfhawkes_fused<<<HK_NBLK, HK_WPB * 32>>>(ids, times, mask, emb, u_table, beta, out);
}

// round 16
// speedup vs baseline: 1.5055x; 1.5055x over previous
#include <cuda_runtime.h>
#include <math.h>

// MFHawkes factorized O(B*L*D): 1 cluster per batch, HW cluster barrier.
//   t = times/1e4, ab = |beta|, ep_i = exp(ab*t_i), C = exp(-ab*t_last)
//   w_j = ep_j*mask_j ; g_j = 1 - ep_j*C ; P_i = sum_{j<i} w_j e_j
//   v = sum_j g_j e_j ; E = sum_i e_i
//   -log(lam_i) = -log(|ab*(e_i.P_i) + u_i*ep_i| + 1e-6*ep_i) + ab*t_i
//   out[b] = sum_i(-log lam_i) + ab*sum(t) + horizon*sum(u) + E.v

#define HK_L     2048
#define HK_D     64
#define HK_B     4
#define HK_CHUNK 16                     // events per warp
#define HK_WPB   16                     // warps per block (512 threads)
#define HK_EPB   (HK_WPB * HK_CHUNK)    // 256 events per block
#define HK_BPB   (HK_L / HK_EPB)        // 8 blocks per batch = cluster size
#define HK_NBLK  (HK_B * HK_BPB)        // 32 blocks

__device__ float g_T[HK_NBLK * HK_D];
__device__ float g_V[HK_NBLK * HK_D];
__device__ float g_E[HK_NBLK * HK_D];

__global__ __launch_bounds__(HK_WPB * 32, 1) __cluster_dims__(HK_BPB, 1, 1)
void mfhawkes_fused(const int*   __restrict__ ids,
                    const float* __restrict__ times,
                    const float* __restrict__ mask,
                    const float* __restrict__ emb,
                    const float* __restrict__ u_table,
                    const float* __restrict__ beta,
                    float*       __restrict__ out)
{
    __shared__ float Tsm[HK_WPB][HK_D];
    __shared__ float Vsm[HK_WPB][HK_D];
    __shared__ float Esm[HK_WPB][HK_D];
    __shared__ float basesm[HK_D];
    __shared__ float prodsm[HK_D];
    __shared__ float racc[HK_WPB];

    const int tid    = threadIdx.x;
    const int warp   = tid >> 5;
    const int lane   = tid & 31;
    const int batch  = blockIdx.x / HK_BPB;
    const int blk_in = blockIdx.x % HK_BPB;

    const float ab      = fabsf(beta[0]);
    const float tlast   = times[batch * HK_L + HK_L - 1] * (1.0f / 10000.0f);
    const float horizon = tlast - times[batch * HK_L + 1] * (1.0f / 10000.0f);
    const float C       = __expf(-ab * tlast);

    if (blk_in == 0 && tid == 0) out[batch] = 0.0f;  // ordered before peers' adds by cluster barrier

    // ---- Phase A: stage uniform data (front-batched vector LDGs)
    const int i0 = batch * HK_L + blk_in * HK_EPB + warp * HK_CHUNK;  // mult of 16

    int   idr[HK_CHUNK];
    float tr[HK_CHUNK], mr[HK_CHUNK];
    #pragma unroll
    for (int q = 0; q < HK_CHUNK / 4; q++) {
        const int4   iv = ((const int4*)  (ids   + i0))[q];
        const float4 tv = ((const float4*)(times + i0))[q];
        const float4 mv = ((const float4*)(mask  + i0))[q];
        idr[4*q+0] = iv.x; idr[4*q+1] = iv.y; idr[4*q+2] = iv.z; idr[4*q+3] = iv.w;
        tr [4*q+0] = tv.x; tr [4*q+1] = tv.y; tr [4*q+2] = tv.z; tr [4*q+3] = tv.w;
        mr [4*q+0] = mv.x; mr [4*q+1] = mv.y; mr [4*q+2] = mv.z; mr [4*q+3] = mv.w;
    }

    float e0[HK_CHUNK], e1[HK_CHUNK], w[HK_CHUNK], ue[HK_CHUNK], pe[HK_CHUNK];
    float T0 = 0.f, T1 = 0.f, V0 = 0.f, V1 = 0.f, E0 = 0.f, E1 = 0.f;
    float tsum = 0.f, usum = 0.f;

    // two half-chunks: pure-load batch (24 independent LDGs) then math
    #pragma unroll
    for (int h = 0; h < 2; h++) {
        float uu[HK_CHUNK / 2];
        #pragma unroll
        for (int j = 0; j < HK_CHUNK / 2; j++) {
            const int i  = h * (HK_CHUNK / 2) + j;
            const int id = idr[i];
            e0[i] = emb[id * HK_D + lane];
            e1[i] = emb[id * HK_D + lane + 32];
            uu[j] = u_table[id];
        }
        #pragma unroll
        for (int j = 0; j < HK_CHUNK / 2; j++) {
            const int   i   = h * (HK_CHUNK / 2) + j;
            const float ti  = tr[i] * (1.0f / 10000.0f);
            const float epi = __expf(ab * ti);
            const float au  = fabsf(uu[j]);
            w[i]  = epi * mr[i];
            ue[i] = au * epi;
            pe[i] = 1e-6f * epi;
            const float g = 1.0f - epi * C;
            T0 += w[i] * e0[i];  T1 += w[i] * e1[i];
            V0 += g    * e0[i];  V1 += g    * e1[i];
            E0 += e0[i];         E1 += e1[i];
            tsum += ti;  usum += au;
        }
    }
    Tsm[warp][lane] = T0;  Tsm[warp][lane + 32] = T1;
    Vsm[warp][lane] = V0;  Vsm[warp][lane + 32] = V1;
    Esm[warp][lane] = E0;  Esm[warp][lane + 32] = E1;
    __syncthreads();

    // ---- publish block totals
    if (tid < HK_D) {
        const int d = tid;
        float tt = 0.f, vv = 0.f, ee = 0.f;
        #pragma unroll
        for (int c = 0; c < HK_WPB; c++) {
            tt += Tsm[c][d];
            vv += Vsm[c][d];
            ee += Esm[c][d];
        }
        g_T[blockIdx.x * HK_D + d] = tt;
        g_V[blockIdx.x * HK_D + d] = vv;
        g_E[blockIdx.x * HK_D + d] = ee;
    }

    // ---- hardware cluster barrier (release/acquire at cluster scope)
    asm volatile("barrier.cluster.arrive.aligned;" ::: "memory");
    asm volatile("barrier.cluster.wait.aligned;"   ::: "memory");

    // ---- cross-block exclusive base (fully unrolled, predicated adds = max MLP)
    if (tid < HK_D) {
        const int d = tid;
        float base = 0.f;
        #pragma unroll
        for (int k = 0; k < HK_BPB; k++) {
            const float tb = g_T[(batch * HK_BPB + k) * HK_D + d];
            if (k < blk_in) base += tb;
        }
        basesm[d] = base;
        if (blk_in == 0) {
            float vv = 0.f, ee = 0.f;
            #pragma unroll
            for (int k = 0; k < HK_BPB; k++) {
                vv += g_V[(batch * HK_BPB + k) * HK_D + d];
                ee += g_E[(batch * HK_BPB + k) * HK_D + d];
            }
            prodsm[d] = vv * ee;
        }
    }
    __syncthreads();

    // ---- Phase C: per-warp base, FFMA P-chain, batched reduce, fused logs
    {
        float P0 = basesm[lane];
        float P1 = basesm[lane + 32];
        #pragma unroll
        for (int c = 0; c < HK_WPB - 1; c++) {
            const float a0 = Tsm[c][lane];
            const float a1 = Tsm[c][lane + 32];
            if (c < warp) { P0 += a0; P1 += a1; }
        }
        float d1[HK_CHUNK];
        #pragma unroll
        for (int i = 0; i < HK_CHUNK; i++) {
            d1[i] = e0[i] * P0 + e1[i] * P1;
            P0 += w[i] * e0[i];
            P1 += w[i] * e1[i];
        }
        #pragma unroll
        for (int off = 16; off; off >>= 1) {
            #pragma unroll
            for (int i = 0; i < HK_CHUNK; i++)
                d1[i] += __shfl_xor_sync(0xffffffffu, d1[i], off);
        }
        // tail: acc = ab*sum(t) + horizon*sum(u) - sum(log(arg)), logs fused 4-wide
        float acc = ab * tsum + horizon * usum;
        #pragma unroll
        for (int gq = 0; gq < HK_CHUNK / 4; gq++) {
            float p = 1.0f;
            #pragma unroll
            for (int j = 0; j < 4; j++) {
                const int   i   = gq * 4 + j;
                const float A   = ab * d1[i] + ue[i];
                const float arg = fabsf(A) + pe[i];
                p *= arg;
            }
            acc -= __logf(p);
        }
        if (lane == 0) racc[warp] = acc;
    }
    __syncthreads();

    if (warp == 0) {
        float a = (lane < HK_WPB) ? racc[lane] : 0.f;
        #pragma unroll
        for (int off = 8; off; off >>= 1)
            a += __shfl_xor_sync(0xffffffffu, a, off);
        float extra = 0.f;
        if (blk_in == 0) {
            float p = prodsm[lane] + prodsm[lane + 32];
            #pragma unroll
            for (int off = 16; off; off >>= 1)
                p += __shfl_xor_sync(0xffffffffu, p, off);
            extra = p;
        }
        if (lane == 0) atomicAdd(&out[batch], a + extra);
    }
}

extern "C" void kernel_launch(void* const* d_in, const int* in_sizes, int n_in,
                              void* d_out, int out_size)
{
    const int*   ids     = (const int*)  d_in[0];
    const float* times   = (const float*)d_in[1];
    const float* mask    = (const float*)d_in[2];
    const float* emb     = (const float*)d_in[3];
    const float* u_table = (const float*)d_in[4];
    const float* beta    = (const float*)d_in[5];
    float*       out     = (float*)d_out;

    mfhawkes_fused<<<HK_NBLK, HK_WPB * 32>>>(ids, times, mask, emb, u_table, beta, out);
}